// round 8
// baseline (speedup 1.0000x reference)
#include <cuda_runtime.h>
#include <cuda_bf16.h>
#include <cstdint>
#include <cstddef>

// Shapes (fixed)
#define BW 64
#define BO 64
#define TW 32
#define TO 36
#define DD 512
#define NTILE (BW * BO)

// Swizzled tile layout for w/u: row r (512 floats = 128 float4-words), word k4
// stored at  r*128 + (k4 ^ ((r>>2)&7)).  For LDS.128 with 4-row-strided lanes
// this spreads the 8 distinct words over 8 bank-quads -> conflict-free.
#define SWZW(r, k4) ((((r) * 128) + ((k4) ^ (((r) >> 2) & 7))) * 4)

// dynamic smem layout (float offsets)
#define OFF_U 16384                    // w: 32*512
#define OFF_O (OFF_U + 18432)          // u: 36*512
#define OFF_PART (OFF_O + 18432)       // o: 36*512 (linear)
#define SMEM_FLOATS (OFF_PART + 3456)  // part: 3*1152
#define SMEM_BYTES (SMEM_FLOATS * 4)   // 226,816 B <= 232,448

// scratch
__device__ float g_logits[BW * TW * BO];  // [w][t][b]
__device__ float g_wloss[BW];

__device__ __forceinline__ void cpa16(float* s, const float* g) {
    uint32_t sa = (uint32_t)__cvta_generic_to_shared(s);
    asm volatile("cp.async.cg.shared.global [%0], [%1], 16;" :: "r"(sa), "l"(g));
}
__device__ __forceinline__ void cp_commit() { asm volatile("cp.async.commit_group;"); }
__device__ __forceinline__ void cp_wait0()  { asm volatile("cp.async.wait_group 0;"); }
__device__ __forceinline__ void cp_wait1()  { asm volatile("cp.async.wait_group 1;"); }

__global__ void __launch_bounds__(512, 1)
cap_main(const float* __restrict__ o_g, const float* __restrict__ u_g,
         const float* __restrict__ w_g,
         float* __restrict__ att_out, float* __restrict__ avo_out)
{
    extern __shared__ float sm[];
    float* w_s    = sm;                 // [32][512] swizzled
    float* u_s    = sm + OFF_U;         // [36][512] swizzled
    float* o_s    = sm + OFF_O;         // [36][512] linear
    float* part   = sm + OFF_PART;      // [3][36][32] k-split partials (groups 1..3)
    float* att_ts = part;               // [36][36] overlays part
    float* lp     = part + 1296;        // [2][32] logits partials

    const int tid  = threadIdx.x;
    const int lane = tid & 31;
    const int warp = tid >> 5;

    // tile range (wb-major -> w reuse)
    const int nblk  = gridDim.x;
    const int r     = blockIdx.x;
    const int bas   = NTILE / nblk, rem = NTILE % nblk;
    const int cnt   = bas + (r < rem ? 1 : 0);
    const int start = r * bas + (r < rem ? r : rem);

    // ---- prologue: load w(wb0) and u(b0), swizzled ----
    {
        const int tile0 = start;
        const int wb0 = tile0 >> 6, b0 = tile0 & 63;
        const float* wg = w_g + (size_t)wb0 * TW * DD;
        const float* ug = u_g + (size_t)b0 * TO * DD;
        for (int i = tid; i < TW * 128; i += 512) {
            int t = i >> 7, k4 = i & 127;
            cpa16(&w_s[SWZW(t, k4)], wg + t * DD + k4 * 4);
        }
        for (int i = tid; i < TO * 128; i += 512) {
            int t = i >> 7, k4 = i & 127;
            cpa16(&u_s[SWZW(t, k4)], ug + t * DD + k4 * 4);
        }
        cp_commit(); cp_wait0(); __syncthreads();
    }

    for (int it = 0; it < cnt; ++it) {
        const int tile = start + it;
        const int wb = tile >> 6, b = tile & 63;

        if (it) { cp_wait0(); __syncthreads(); }   // u (+w) prefetch landed

        // ---- (A) prefetch o(b) into o_s, linear (overlaps stage 1) ----
        {
            const float* og = o_g + (size_t)b * TO * DD;
            for (int i = tid; i < TO * 128; i += 512) {
                int t = i >> 7, k4 = i & 127;
                cpa16(&o_s[t * DD + k4 * 4], og + t * DD + k4 * 4);
            }
            cp_commit();                            // group O
        }

        // ---- stage 1: scores(32x36) = w . u^T, 4-way K-split, 4x4 tiles ----
        float s1acc[4][4];
        int t0a = 0, o0a = 0;
        if (tid < 288) {
            const int g    = tid / 72;
            const int id72 = tid % 72;
            const int oc   = id72 >> 3;      // 0..8
            const int tr   = id72 & 7;       // 0..7
            t0a = tr * 4; o0a = oc * 4;
            const int kxa = tr & 7;          // A row-group xor
            const int kx  = kxa ^ (oc & 7);  // A-index -> B-index xor

            // base pointers: iterate A's stored word index linearly
            const float* baseA[4];
            const float* baseB[4];
            #pragma unroll
            for (int i = 0; i < 4; i++)
                baseA[i] = w_s + (t0a + i) * 512 + g * 128;
            #pragma unroll
            for (int j = 0; j < 4; j++)
                baseB[j] = u_s + (o0a + j) * 512 + g * 128;

            #pragma unroll
            for (int i = 0; i < 4; i++)
                #pragma unroll
                for (int j = 0; j < 4; j++) s1acc[i][j] = 0.f;

            #pragma unroll 2
            for (int kk = 0; kk < 32; kk++) {
                const int offB = (kk ^ kx) << 2;
                float4 aq[4], bq[4];
                #pragma unroll
                for (int i = 0; i < 4; i++) aq[i] = *(const float4*)(baseA[i] + (kk << 2));
                #pragma unroll
                for (int j = 0; j < 4; j++) bq[j] = *(const float4*)(baseB[j] + offB);
                #pragma unroll
                for (int i = 0; i < 4; i++) {
                    #pragma unroll
                    for (int j = 0; j < 4; j++) {
                        s1acc[i][j] += aq[i].x * bq[j].x;
                        s1acc[i][j] += aq[i].y * bq[j].y;
                        s1acc[i][j] += aq[i].z * bq[j].z;
                        s1acc[i][j] += aq[i].w * bq[j].w;
                    }
                }
            }
            if (g) {  // groups 1..3 spill partials; group 0 keeps registers
                float* pg = part + (g - 1) * 1152;
                #pragma unroll
                for (int i = 0; i < 4; i++)
                    #pragma unroll
                    for (int j = 0; j < 4; j++)
                        pg[(o0a + j) * 32 + (t0a + i)] = s1acc[i][j];
            }
        }
        __syncthreads();

        // ---- (D) prefetch u(next) into u_s (swizzled) ----
        {
            const int ntile = (it + 1 < cnt) ? tile + 1 : tile;
            const int nb = ntile & 63;
            const float* ug = u_g + (size_t)nb * TO * DD;
            for (int i = tid; i < TO * 128; i += 512) {
                int t = i >> 7, k4 = i & 127;
                cpa16(&u_s[SWZW(t, k4)], ug + t * DD + k4 * 4);
            }
            cp_commit();                            // group U
        }

        // ---- reduce K-split partials into group-0 registers, scale ----
        const float scale = 0.044194173824159216f;  // 1/sqrt(512)
        if (tid < 72) {
            #pragma unroll
            for (int i = 0; i < 4; i++)
                #pragma unroll
                for (int j = 0; j < 4; j++) {
                    const int idx = (o0a + j) * 32 + (t0a + i);
                    s1acc[i][j] = (s1acc[i][j] + part[idx] + part[1152 + idx]
                                   + part[2304 + idx]) * scale;
                }
        }
        __syncthreads();
        if (tid < 72) {
            #pragma unroll
            for (int i = 0; i < 4; i++)
                #pragma unroll
                for (int j = 0; j < 4; j++)
                    att_ts[(o0a + j) * 36 + (t0a + i)] = s1acc[i][j];
        }
        __syncthreads();

        // ---- softmax over To; warp handles t = warp and warp+16 ----
        #pragma unroll
        for (int rr = 0; rr < 2; rr++) {
            const int t = warp + rr * 16;
            float v0 = att_ts[lane * 36 + t];
            float v1 = (lane < 4) ? att_ts[(32 + lane) * 36 + t] : -3.4e38f;
            float mx = fmaxf(v0, v1);
            #pragma unroll
            for (int off = 16; off; off >>= 1) mx = fmaxf(mx, __shfl_xor_sync(0xffffffffu, mx, off));
            float e0 = __expf(v0 - mx);
            float e1 = (lane < 4) ? __expf(v1 - mx) : 0.f;
            float s = e0 + e1;
            #pragma unroll
            for (int off = 16; off; off >>= 1) s += __shfl_xor_sync(0xffffffffu, s, off);
            float rs = __frcp_rn(s);
            float p0 = e0 * rs;
            att_ts[lane * 36 + t] = p0;
            float* ao = att_out + ((size_t)((wb * BO + b) * TW + t)) * TO;
            ao[lane] = p0;
            if (lane < 4) {
                float p1 = e1 * rs;
                att_ts[(32 + lane) * 36 + t] = p1;
                ao[32 + lane] = p1;
            }
        }
        cp_wait1();                                 // group O done (U may still fly)
        __syncthreads();

        // ---- stage 2: att_V_o = att(32x36).o(36x512), column-strided; fused logits ----
        const int tr2 = tid >> 6;      // t-tile 0..7
        const int c   = tid & 63;      // column lane 0..63
        const int t0  = tr2 * 4;
        float acc2[4][8];
        #pragma unroll
        for (int i = 0; i < 4; i++)
            #pragma unroll
            for (int j = 0; j < 8; j++) acc2[i][j] = 0.f;

        #pragma unroll 4
        for (int o = 0; o < 36; o++) {
            float4 a = *(const float4*)&att_ts[o * 36 + t0];   // warp-uniform broadcast
            float ov[8];
            #pragma unroll
            for (int j = 0; j < 8; j++) ov[j] = o_s[o * DD + c + 64 * j];  // dense, no conflict
            float av[4] = {a.x, a.y, a.z, a.w};
            #pragma unroll
            for (int i = 0; i < 4; i++)
                #pragma unroll
                for (int j = 0; j < 8; j++)
                    acc2[i][j] += av[i] * ov[j];
        }

        // dense warp STG.32 stores + swizzle-aware w reads for logits
        float* avo = avo_out + ((size_t)((wb * BO + b) * TW + t0)) * DD;
        const int cb = (((c >> 2) ^ tr2) << 2) + (c & 3);   // swizzled in-row float offset
        #pragma unroll
        for (int i = 0; i < 4; i++) {
            float* row = avo + (size_t)i * DD;
            #pragma unroll
            for (int j = 0; j < 8; j++)
                row[c + 64 * j] = acc2[i][j];

            const float* wr = w_s + (t0 + i) * 512 + cb;
            float l = 0.f;
            #pragma unroll
            for (int j = 0; j < 8; j++)
                l += acc2[i][j] * wr[64 * j];
            #pragma unroll
            for (int off = 16; off; off >>= 1) l += __shfl_xor_sync(0xffffffffu, l, off);
            if (lane == 0) lp[(warp & 1) * 32 + (t0 + i)] = l;
        }
        __syncthreads();
        if (tid < 32)
            g_logits[((size_t)wb * TW + tid) * BO + b] = lp[tid] + lp[32 + tid];

        // ---- (H) prefetch w if wb changes ----
        if (it + 1 < cnt) {
            const int nwb = (tile + 1) >> 6;
            if (nwb != wb) {
                const float* wg = w_g + (size_t)nwb * TW * DD;
                for (int i = tid; i < TW * 128; i += 512) {
                    int t = i >> 7, k4 = i & 127;
                    cpa16(&w_s[SWZW(t, k4)], wg + t * DD + k4 * 4);
                }
                cp_commit();                        // group W
            }
        }
    }
    cp_wait0();
}

// ---- loss, stage 1: per-w masked mean of (diag - lse) ----
__global__ void cap_loss1(const int* __restrict__ mask)
{
    __shared__ float sacc[8], scnt[8];
    const int w = blockIdx.x;
    const int tid = threadIdx.x, warp = tid >> 5, lane = tid & 31;
    const float* lw = g_logits + (size_t)w * TW * BO;
    float acc = 0.f, cntv = 0.f;
    for (int t = warp; t < TW; t += 8) {
        float v0 = lw[t * BO + lane];
        float v1 = lw[t * BO + 32 + lane];
        float mx = fmaxf(v0, v1);
        #pragma unroll
        for (int off = 16; off; off >>= 1) mx = fmaxf(mx, __shfl_xor_sync(0xffffffffu, mx, off));
        float s = expf(v0 - mx) + expf(v1 - mx);
        #pragma unroll
        for (int off = 16; off; off >>= 1) s += __shfl_xor_sync(0xffffffffu, s, off);
        if (lane == 0 && mask[w * TW + t] == 0) {
            acc += lw[t * BO + w] - (mx + logf(s));
            cntv += 1.f;
        }
    }
    if (lane == 0) { sacc[warp] = acc; scnt[warp] = cntv; }
    __syncthreads();
    if (tid == 0) {
        float a = 0.f, c = 0.f;
        #pragma unroll
        for (int i = 0; i < 8; i++) { a += sacc[i]; c += scnt[i]; }
        g_wloss[w] = a / (c + 1e-6f);
    }
}

// ---- loss, stage 2: -mean over w ----
__global__ void cap_loss2(float* __restrict__ out)
{
    __shared__ float sh[2];
    const int tid = threadIdx.x, lane = tid & 31, warp = tid >> 5;
    float v = g_wloss[tid];
    #pragma unroll
    for (int off = 16; off; off >>= 1) v += __shfl_xor_sync(0xffffffffu, v, off);
    if (lane == 0) sh[warp] = v;
    __syncthreads();
    if (tid == 0) out[0] = -(sh[0] + sh[1]) * (1.0f / 64.0f);
}

extern "C" void kernel_launch(void* const* d_in, const int* in_sizes, int n_in,
                              void* d_out, int out_size)
{
    (void)in_sizes; (void)n_in; (void)out_size;
    const float* o_g  = (const float*)d_in[0];
    const float* u_g  = (const float*)d_in[1];
    const float* w_g  = (const float*)d_in[2];
    const int*   mask = (const int*)d_in[3];
    float* out = (float*)d_out;

    static int nsm = 0;
    if (nsm == 0) {
        int dev = 0;
        cudaGetDevice(&dev);
        cudaDeviceGetAttribute(&nsm, cudaDevAttrMultiProcessorCount, dev);
        if (nsm <= 0) nsm = 148;
        cudaFuncSetAttribute(cap_main, cudaFuncAttributeMaxDynamicSharedMemorySize, SMEM_BYTES);
    }

    // output layout: [0]=loss, att (Bw,Bo,Tw,To), att_V_o (Bw,Bo,Tw,D)
    float* att_out = out + 1;
    float* avo_out = out + 1 + (size_t)BW * BO * TW * TO;

    cap_main<<<nsm, 512, SMEM_BYTES>>>(o_g, u_g, w_g, att_out, avo_out);
    cap_loss1<<<64, 256>>>(mask);
    cap_loss2<<<1, 64>>>(out);
}

// round 9
// speedup vs baseline: 2.2425x; 2.2425x over previous
#include <cuda_runtime.h>
#include <cuda_bf16.h>
#include <cstdint>
#include <cstddef>

// Shapes (fixed)
#define BW 64
#define BO 64
#define TW 32
#define TO 36
#define DD 512
#define NTILE (BW * BO)

// Swizzled tile layout for w/u: row r (512 floats = 128 float4-words):
// logical word k4 stored at  r*128 + (k4 ^ ((r>>2)&7)).
// Readers iterate LOGICAL k and apply the XOR in the address, so
// row-group-strided lanes hit 8 distinct bank-quads (conflict-free).
#define SWZW(r, k4) ((((r) * 128) + ((k4) ^ (((r) >> 2) & 7))) * 4)

// dynamic smem layout (float offsets)
#define OFF_U 16384                    // w: 32*512 swizzled
#define OFF_O (OFF_U + 18432)          // u: 36*512 swizzled
#define OFF_PART (OFF_O + 18432)       // o: 36*512 linear
#define SMEM_FLOATS (OFF_PART + 3456)  // part: 3*1152
#define SMEM_BYTES (SMEM_FLOATS * 4)   // 226,816 B <= 232,448

// scratch
__device__ float g_logits[BW * TW * BO];  // [w][t][b]
__device__ float g_wloss[BW];

__device__ __forceinline__ void cpa16(float* s, const float* g) {
    uint32_t sa = (uint32_t)__cvta_generic_to_shared(s);
    asm volatile("cp.async.cg.shared.global [%0], [%1], 16;" :: "r"(sa), "l"(g));
}
__device__ __forceinline__ void cp_commit() { asm volatile("cp.async.commit_group;"); }
__device__ __forceinline__ void cp_wait0()  { asm volatile("cp.async.wait_group 0;"); }
__device__ __forceinline__ void cp_wait1()  { asm volatile("cp.async.wait_group 1;"); }

__global__ void __launch_bounds__(512, 1)
cap_main(const float* __restrict__ o_g, const float* __restrict__ u_g,
         const float* __restrict__ w_g,
         float* __restrict__ att_out, float* __restrict__ avo_out)
{
    extern __shared__ float sm[];
    float* w_s    = sm;                 // [32][512] swizzled
    float* u_s    = sm + OFF_U;         // [36][512] swizzled
    float* o_s    = sm + OFF_O;         // [36][512] linear
    float* part   = sm + OFF_PART;      // [3][36][32] k-split partials (groups 1..3)
    float* att_ts = part;               // [36][36] overlays part
    float* lp     = part + 1296;        // [2][32] logits partials

    const int tid  = threadIdx.x;
    const int lane = tid & 31;
    const int warp = tid >> 5;

    // tile range (wb-major -> w reuse)
    const int nblk  = gridDim.x;
    const int r     = blockIdx.x;
    const int bas   = NTILE / nblk, rem = NTILE % nblk;
    const int cnt   = bas + (r < rem ? 1 : 0);
    const int start = r * bas + (r < rem ? r : rem);

    // ---- prologue: load w(wb0) and u(b0), swizzled ----
    {
        const int tile0 = start;
        const int wb0 = tile0 >> 6, b0 = tile0 & 63;
        const float* wg = w_g + (size_t)wb0 * TW * DD;
        const float* ug = u_g + (size_t)b0 * TO * DD;
        for (int i = tid; i < TW * 128; i += 512) {
            int t = i >> 7, k4 = i & 127;
            cpa16(&w_s[SWZW(t, k4)], wg + t * DD + k4 * 4);
        }
        for (int i = tid; i < TO * 128; i += 512) {
            int t = i >> 7, k4 = i & 127;
            cpa16(&u_s[SWZW(t, k4)], ug + t * DD + k4 * 4);
        }
        cp_commit(); cp_wait0(); __syncthreads();
    }

    for (int it = 0; it < cnt; ++it) {
        const int tile = start + it;
        const int wb = tile >> 6, b = tile & 63;

        if (it) { cp_wait0(); __syncthreads(); }   // u (+w) prefetch landed

        // ---- (A) prefetch o(b) into o_s, linear (overlaps stage 1) ----
        {
            const float* og = o_g + (size_t)b * TO * DD;
            for (int i = tid; i < TO * 128; i += 512) {
                int t = i >> 7, k4 = i & 127;
                cpa16(&o_s[t * DD + k4 * 4], og + t * DD + k4 * 4);
            }
            cp_commit();                            // group O
        }

        // ---- stage 1: scores(32x36) = w . u^T, 4-way K-split, 4x4 tiles ----
        // Logical-k iteration; per-operand XOR in the ADDRESS:
        //   A rows 4tr..4tr+3 -> xor tr   (8 distinct quads per 8-lane phase)
        //   B rows 4oc..4oc+3 -> xor oc&7 (identical addr per phase -> broadcast)
        float s1acc[4][4];
        int t0a = 0, o0a = 0;
        if (tid < 288) {
            const int g    = tid / 72;
            const int id72 = tid % 72;
            const int oc   = id72 >> 3;      // 0..8
            const int tr   = id72 & 7;       // 0..7
            t0a = tr * 4; o0a = oc * 4;
            const int axor = tr;
            const int bxor = oc & 7;

            const float* baseA[4];
            const float* baseB[4];
            #pragma unroll
            for (int i = 0; i < 4; i++)
                baseA[i] = w_s + (t0a + i) * 512 + g * 128;
            #pragma unroll
            for (int j = 0; j < 4; j++)
                baseB[j] = u_s + (o0a + j) * 512 + g * 128;

            #pragma unroll
            for (int i = 0; i < 4; i++)
                #pragma unroll
                for (int j = 0; j < 4; j++) s1acc[i][j] = 0.f;

            #pragma unroll 2
            for (int kk = 0; kk < 32; kk++) {
                const int offA = ((kk ^ axor) << 2);
                const int offB = ((kk ^ bxor) << 2);
                float4 aq[4], bq[4];
                #pragma unroll
                for (int i = 0; i < 4; i++) aq[i] = *(const float4*)(baseA[i] + offA);
                #pragma unroll
                for (int j = 0; j < 4; j++) bq[j] = *(const float4*)(baseB[j] + offB);
                #pragma unroll
                for (int i = 0; i < 4; i++) {
                    #pragma unroll
                    for (int j = 0; j < 4; j++) {
                        s1acc[i][j] += aq[i].x * bq[j].x;
                        s1acc[i][j] += aq[i].y * bq[j].y;
                        s1acc[i][j] += aq[i].z * bq[j].z;
                        s1acc[i][j] += aq[i].w * bq[j].w;
                    }
                }
            }
            if (g) {  // groups 1..3 spill partials; group 0 keeps registers
                float* pg = part + (g - 1) * 1152;
                #pragma unroll
                for (int i = 0; i < 4; i++)
                    #pragma unroll
                    for (int j = 0; j < 4; j++)
                        pg[(o0a + j) * 32 + (t0a + i)] = s1acc[i][j];
            }
        }
        __syncthreads();

        // ---- (D) prefetch u(next) into u_s (swizzled) ----
        {
            const int ntile = (it + 1 < cnt) ? tile + 1 : tile;
            const int nb = ntile & 63;
            const float* ug = u_g + (size_t)nb * TO * DD;
            for (int i = tid; i < TO * 128; i += 512) {
                int t = i >> 7, k4 = i & 127;
                cpa16(&u_s[SWZW(t, k4)], ug + t * DD + k4 * 4);
            }
            cp_commit();                            // group U
        }

        // ---- reduce K-split partials into group-0 registers, scale ----
        const float scale = 0.044194173824159216f;  // 1/sqrt(512)
        if (tid < 72) {
            #pragma unroll
            for (int i = 0; i < 4; i++)
                #pragma unroll
                for (int j = 0; j < 4; j++) {
                    const int idx = (o0a + j) * 32 + (t0a + i);
                    s1acc[i][j] = (s1acc[i][j] + part[idx] + part[1152 + idx]
                                   + part[2304 + idx]) * scale;
                }
        }
        __syncthreads();
        if (tid < 72) {
            #pragma unroll
            for (int i = 0; i < 4; i++)
                #pragma unroll
                for (int j = 0; j < 4; j++)
                    att_ts[(o0a + j) * 36 + (t0a + i)] = s1acc[i][j];
        }
        __syncthreads();

        // ---- softmax over To; warp handles t = warp and warp+16 ----
        #pragma unroll
        for (int rr = 0; rr < 2; rr++) {
            const int t = warp + rr * 16;
            float v0 = att_ts[lane * 36 + t];
            float v1 = (lane < 4) ? att_ts[(32 + lane) * 36 + t] : -3.4e38f;
            float mx = fmaxf(v0, v1);
            #pragma unroll
            for (int off = 16; off; off >>= 1) mx = fmaxf(mx, __shfl_xor_sync(0xffffffffu, mx, off));
            float e0 = __expf(v0 - mx);
            float e1 = (lane < 4) ? __expf(v1 - mx) : 0.f;
            float s = e0 + e1;
            #pragma unroll
            for (int off = 16; off; off >>= 1) s += __shfl_xor_sync(0xffffffffu, s, off);
            float rs = __frcp_rn(s);
            float p0 = e0 * rs;
            att_ts[lane * 36 + t] = p0;
            float* ao = att_out + ((size_t)((wb * BO + b) * TW + t)) * TO;
            ao[lane] = p0;
            if (lane < 4) {
                float p1 = e1 * rs;
                att_ts[(32 + lane) * 36 + t] = p1;
                ao[32 + lane] = p1;
            }
        }
        cp_wait1();                                 // group O done (U may still fly)
        __syncthreads();

        // ---- stage 2: att_V_o = att(32x36).o(36x512), column-strided; fused logits ----
        const int tr2 = tid >> 6;      // t-tile 0..7
        const int c   = tid & 63;      // column lane 0..63
        const int t0  = tr2 * 4;
        float acc2[4][8];
        #pragma unroll
        for (int i = 0; i < 4; i++)
            #pragma unroll
            for (int j = 0; j < 8; j++) acc2[i][j] = 0.f;

        #pragma unroll 4
        for (int o = 0; o < 36; o++) {
            float4 a = *(const float4*)&att_ts[o * 36 + t0];   // warp-uniform broadcast
            float ov[8];
            #pragma unroll
            for (int j = 0; j < 8; j++) ov[j] = o_s[o * DD + c + 64 * j];  // dense, no conflict
            float av[4] = {a.x, a.y, a.z, a.w};
            #pragma unroll
            for (int i = 0; i < 4; i++)
                #pragma unroll
                for (int j = 0; j < 8; j++)
                    acc2[i][j] += av[i] * ov[j];
        }

        // dense warp STG.32 stores + swizzle-aware w reads for logits
        float* avo = avo_out + ((size_t)((wb * BO + b) * TW + t0)) * DD;
        const int cb = (((c >> 2) ^ tr2) << 2) + (c & 3);   // swizzled in-row float offset
        #pragma unroll
        for (int i = 0; i < 4; i++) {
            float* row = avo + (size_t)i * DD;
            #pragma unroll
            for (int j = 0; j < 8; j++)
                row[c + 64 * j] = acc2[i][j];

            const float* wr = w_s + (t0 + i) * 512 + cb;
            float l = 0.f;
            #pragma unroll
            for (int j = 0; j < 8; j++)
                l += acc2[i][j] * wr[64 * j];
            #pragma unroll
            for (int off = 16; off; off >>= 1) l += __shfl_xor_sync(0xffffffffu, l, off);
            if (lane == 0) lp[(warp & 1) * 32 + (t0 + i)] = l;
        }
        __syncthreads();
        if (tid < 32)
            g_logits[((size_t)wb * TW + tid) * BO + b] = lp[tid] + lp[32 + tid];

        // ---- (H) prefetch w if wb changes ----
        if (it + 1 < cnt) {
            const int nwb = (tile + 1) >> 6;
            if (nwb != wb) {
                const float* wg = w_g + (size_t)nwb * TW * DD;
                for (int i = tid; i < TW * 128; i += 512) {
                    int t = i >> 7, k4 = i & 127;
                    cpa16(&w_s[SWZW(t, k4)], wg + t * DD + k4 * 4);
                }
                cp_commit();                        // group W
            }
        }
    }
    cp_wait0();
}

// ---- loss, stage 1: per-w masked mean of (diag - lse) ----
__global__ void cap_loss1(const int* __restrict__ mask)
{
    __shared__ float sacc[8], scnt[8];
    const int w = blockIdx.x;
    const int tid = threadIdx.x, warp = tid >> 5, lane = tid & 31;
    const float* lw = g_logits + (size_t)w * TW * BO;
    float acc = 0.f, cntv = 0.f;
    for (int t = warp; t < TW; t += 8) {
        float v0 = lw[t * BO + lane];
        float v1 = lw[t * BO + 32 + lane];
        float mx = fmaxf(v0, v1);
        #pragma unroll
        for (int off = 16; off; off >>= 1) mx = fmaxf(mx, __shfl_xor_sync(0xffffffffu, mx, off));
        float s = expf(v0 - mx) + expf(v1 - mx);
        #pragma unroll
        for (int off = 16; off; off >>= 1) s += __shfl_xor_sync(0xffffffffu, s, off);
        if (lane == 0 && mask[w * TW + t] == 0) {
            acc += lw[t * BO + w] - (mx + logf(s));
            cntv += 1.f;
        }
    }
    if (lane == 0) { sacc[warp] = acc; scnt[warp] = cntv; }
    __syncthreads();
    if (tid == 0) {
        float a = 0.f, c = 0.f;
        #pragma unroll
        for (int i = 0; i < 8; i++) { a += sacc[i]; c += scnt[i]; }
        g_wloss[w] = a / (c + 1e-6f);
    }
}

// ---- loss, stage 2: -mean over w ----
__global__ void cap_loss2(float* __restrict__ out)
{
    __shared__ float sh[2];
    const int tid = threadIdx.x, lane = tid & 31, warp = tid >> 5;
    float v = g_wloss[tid];
    #pragma unroll
    for (int off = 16; off; off >>= 1) v += __shfl_xor_sync(0xffffffffu, v, off);
    if (lane == 0) sh[warp] = v;
    __syncthreads();
    if (tid == 0) out[0] = -(sh[0] + sh[1]) * (1.0f / 64.0f);
}

extern "C" void kernel_launch(void* const* d_in, const int* in_sizes, int n_in,
                              void* d_out, int out_size)
{
    (void)in_sizes; (void)n_in; (void)out_size;
    const float* o_g  = (const float*)d_in[0];
    const float* u_g  = (const float*)d_in[1];
    const float* w_g  = (const float*)d_in[2];
    const int*   mask = (const int*)d_in[3];
    float* out = (float*)d_out;

    static int nsm = 0;
    if (nsm == 0) {
        int dev = 0;
        cudaGetDevice(&dev);
        cudaDeviceGetAttribute(&nsm, cudaDevAttrMultiProcessorCount, dev);
        if (nsm <= 0) nsm = 148;
        cudaFuncSetAttribute(cap_main, cudaFuncAttributeMaxDynamicSharedMemorySize, SMEM_BYTES);
    }

    // output layout: [0]=loss, att (Bw,Bo,Tw,To), att_V_o (Bw,Bo,Tw,D)
    float* att_out = out + 1;
    float* avo_out = out + 1 + (size_t)BW * BO * TW * TO;

    cap_main<<<nsm, 512, SMEM_BYTES>>>(o_g, u_g, w_g, att_out, avo_out);
    cap_loss1<<<64, 256>>>(mask);
    cap_loss2<<<1, 64>>>(out);
}

// round 12
// speedup vs baseline: 2.3141x; 1.0319x over previous
#include <cuda_runtime.h>
#include <cuda_bf16.h>
#include <cstdint>
#include <cstddef>

// Shapes (fixed)
#define BW 64
#define BO 64
#define TW 32
#define TO 36
#define DD 512
#define NTILE (BW * BO)

// Swizzled tile layout for w/u: row r (512 floats = 128 float4-words):
// logical word k4 stored at  r*128 + (k4 ^ ((r>>2)&7)).
// Readers iterate LOGICAL k and apply the XOR in the address.
#define SWZW(r, k4) ((((r) * 128) + ((k4) ^ (((r) >> 2) & 7))) * 4)

// dynamic smem layout (float offsets)
#define OFF_U 16384                    // w: 32*512 swizzled
#define OFF_O (OFF_U + 18432)          // u: 36*512 swizzled
#define OFF_PART (OFF_O + 18432)       // o: 36*512 linear
#define SMEM_FLOATS (OFF_PART + 3456)  // part: 3*1152
#define SMEM_BYTES (SMEM_FLOATS * 4)   // 226,816 B <= 232,448

// scratch
__device__ float g_logits[BW * TW * BO];  // [w][t][b]
__device__ float g_wloss[BW];

__device__ __forceinline__ void cpa16(float* s, const float* g) {
    uint32_t sa = (uint32_t)__cvta_generic_to_shared(s);
    asm volatile("cp.async.cg.shared.global [%0], [%1], 16;" :: "r"(sa), "l"(g));
}
__device__ __forceinline__ void cp_commit() { asm volatile("cp.async.commit_group;"); }
__device__ __forceinline__ void cp_wait0()  { asm volatile("cp.async.wait_group 0;"); }
__device__ __forceinline__ void cp_wait1()  { asm volatile("cp.async.wait_group 1;"); }

// ---- packed fp32x2 helpers (Blackwell dual-fp32 FMA) ----
__device__ __forceinline__ void fma2(unsigned long long& d,
                                     unsigned long long a, unsigned long long b) {
    asm("fma.rn.f32x2 %0, %1, %2, %0;" : "+l"(d) : "l"(a), "l"(b));
}
__device__ __forceinline__ unsigned long long packf2(float lo, float hi) {
    unsigned long long v;
    asm("mov.b64 %0, {%1, %2};" : "=l"(v) : "r"(__float_as_uint(lo)), "r"(__float_as_uint(hi)));
    return v;
}
__device__ __forceinline__ void unpackf2(unsigned long long v, float& lo, float& hi) {
    unsigned a, b;
    asm("mov.b64 {%0, %1}, %2;" : "=r"(a), "=r"(b) : "l"(v));
    lo = __uint_as_float(a); hi = __uint_as_float(b);
}
__device__ __forceinline__ float f2sum(unsigned long long v) {
    float lo, hi; unpackf2(v, lo, hi); return lo + hi;
}

__global__ void __launch_bounds__(512, 1)
cap_main(const float* __restrict__ o_g, const float* __restrict__ u_g,
         const float* __restrict__ w_g,
         float* __restrict__ att_out, float* __restrict__ avo_out)
{
    extern __shared__ float sm[];
    float* w_s    = sm;                 // [32][512] swizzled
    float* u_s    = sm + OFF_U;         // [36][512] swizzled
    float* o_s    = sm + OFF_O;         // [36][512] linear
    float* part   = sm + OFF_PART;      // [3][36][32] k-split partials (groups 1..3)
    float* att_ts = part;               // [36][36] overlays part
    float* lp     = part + 1296;        // [2][32] logits partials

    const int tid  = threadIdx.x;
    const int lane = tid & 31;
    const int warp = tid >> 5;

    // tile range (wb-major -> w reuse)
    const int nblk  = gridDim.x;
    const int r     = blockIdx.x;
    const int bas   = NTILE / nblk, rem = NTILE % nblk;
    const int cnt   = bas + (r < rem ? 1 : 0);
    const int start = r * bas + (r < rem ? r : rem);

    // ---- prologue: load w(wb0) and u(b0), swizzled ----
    {
        const int tile0 = start;
        const int wb0 = tile0 >> 6, b0 = tile0 & 63;
        const float* wg = w_g + (size_t)wb0 * TW * DD;
        const float* ug = u_g + (size_t)b0 * TO * DD;
        for (int i = tid; i < TW * 128; i += 512) {
            int t = i >> 7, k4 = i & 127;
            cpa16(&w_s[SWZW(t, k4)], wg + t * DD + k4 * 4);
        }
        for (int i = tid; i < TO * 128; i += 512) {
            int t = i >> 7, k4 = i & 127;
            cpa16(&u_s[SWZW(t, k4)], ug + t * DD + k4 * 4);
        }
        cp_commit(); cp_wait0(); __syncthreads();
    }

    for (int it = 0; it < cnt; ++it) {
        const int tile = start + it;
        const int wb = tile >> 6, b = tile & 63;

        if (it) { cp_wait0(); __syncthreads(); }   // u (+w) prefetch landed

        // ---- (A) prefetch o(b) into o_s, linear (overlaps stage 1) ----
        {
            const float* og = o_g + (size_t)b * TO * DD;
            for (int i = tid; i < TO * 128; i += 512) {
                int t = i >> 7, k4 = i & 127;
                cpa16(&o_s[t * DD + k4 * 4], og + t * DD + k4 * 4);
            }
            cp_commit();                            // group O
        }

        // ---- stage 1: scores(32x36) = w . u^T, 4-way K-split, 4x4 tiles ----
        // f32x2: pack along k (float4 smem word = 2 packed pairs); one
        // horizontal add per output after the k-loop.
        float s1acc[4][4];
        int t0a = 0, o0a = 0;
        if (tid < 288) {
            const int g    = tid / 72;
            const int id72 = tid % 72;
            const int oc   = id72 >> 3;      // 0..8
            const int tr   = id72 & 7;       // 0..7
            t0a = tr * 4; o0a = oc * 4;
            const int axor = tr;
            const int bxor = oc & 7;

            const float* baseA[4];
            const float* baseB[4];
            #pragma unroll
            for (int i = 0; i < 4; i++)
                baseA[i] = w_s + (t0a + i) * 512 + g * 128;
            #pragma unroll
            for (int j = 0; j < 4; j++)
                baseB[j] = u_s + (o0a + j) * 512 + g * 128;

            unsigned long long accp[4][4];
            #pragma unroll
            for (int i = 0; i < 4; i++)
                #pragma unroll
                for (int j = 0; j < 4; j++) accp[i][j] = 0ull;

            #pragma unroll 2
            for (int kk = 0; kk < 32; kk++) {
                const int offA = ((kk ^ axor) << 2);
                const int offB = ((kk ^ bxor) << 2);
                ulonglong2 aq[4], bq[4];
                #pragma unroll
                for (int i = 0; i < 4; i++) aq[i] = *(const ulonglong2*)(baseA[i] + offA);
                #pragma unroll
                for (int j = 0; j < 4; j++) bq[j] = *(const ulonglong2*)(baseB[j] + offB);
                #pragma unroll
                for (int i = 0; i < 4; i++) {
                    #pragma unroll
                    for (int j = 0; j < 4; j++) {
                        fma2(accp[i][j], aq[i].x, bq[j].x);
                        fma2(accp[i][j], aq[i].y, bq[j].y);
                    }
                }
            }
            #pragma unroll
            for (int i = 0; i < 4; i++)
                #pragma unroll
                for (int j = 0; j < 4; j++)
                    s1acc[i][j] = f2sum(accp[i][j]);

            if (g) {  // groups 1..3 spill partials; group 0 keeps registers
                float* pg = part + (g - 1) * 1152;
                #pragma unroll
                for (int i = 0; i < 4; i++)
                    #pragma unroll
                    for (int j = 0; j < 4; j++)
                        pg[(o0a + j) * 32 + (t0a + i)] = s1acc[i][j];
            }
        }
        __syncthreads();

        // ---- (D) prefetch u(next) into u_s (swizzled) ----
        {
            const int ntile = (it + 1 < cnt) ? tile + 1 : tile;
            const int nb = ntile & 63;
            const float* ug = u_g + (size_t)nb * TO * DD;
            for (int i = tid; i < TO * 128; i += 512) {
                int t = i >> 7, k4 = i & 127;
                cpa16(&u_s[SWZW(t, k4)], ug + t * DD + k4 * 4);
            }
            cp_commit();                            // group U
        }

        // ---- reduce K-split partials into group-0 registers, scale ----
        const float scale = 0.044194173824159216f;  // 1/sqrt(512)
        if (tid < 72) {
            #pragma unroll
            for (int i = 0; i < 4; i++)
                #pragma unroll
                for (int j = 0; j < 4; j++) {
                    const int idx = (o0a + j) * 32 + (t0a + i);
                    s1acc[i][j] = (s1acc[i][j] + part[idx] + part[1152 + idx]
                                   + part[2304 + idx]) * scale;
                }
        }
        __syncthreads();
        if (tid < 72) {
            #pragma unroll
            for (int i = 0; i < 4; i++)
                #pragma unroll
                for (int j = 0; j < 4; j++)
                    att_ts[(o0a + j) * 36 + (t0a + i)] = s1acc[i][j];
        }
        __syncthreads();

        // ---- softmax over To; warp handles t = warp and warp+16 ----
        #pragma unroll
        for (int rr = 0; rr < 2; rr++) {
            const int t = warp + rr * 16;
            float v0 = att_ts[lane * 36 + t];
            float v1 = (lane < 4) ? att_ts[(32 + lane) * 36 + t] : -3.4e38f;
            float mx = fmaxf(v0, v1);
            #pragma unroll
            for (int off = 16; off; off >>= 1) mx = fmaxf(mx, __shfl_xor_sync(0xffffffffu, mx, off));
            float e0 = __expf(v0 - mx);
            float e1 = (lane < 4) ? __expf(v1 - mx) : 0.f;
            float s = e0 + e1;
            #pragma unroll
            for (int off = 16; off; off >>= 1) s += __shfl_xor_sync(0xffffffffu, s, off);
            float rs = __frcp_rn(s);
            float p0 = e0 * rs;
            att_ts[lane * 36 + t] = p0;
            float* ao = att_out + ((size_t)((wb * BO + b) * TW + t)) * TO;
            ao[lane] = p0;
            if (lane < 4) {
                float p1 = e1 * rs;
                att_ts[(32 + lane) * 36 + t] = p1;
                ao[32 + lane] = p1;
            }
        }
        cp_wait1();                                 // group O done (U may still fly)
        __syncthreads();

        // ---- stage 2: att_V_o = att(32x36).o(36x512), column-strided; fused logits ----
        // f32x2: pack along j — packed acc jp holds d = c+64*(2jp) and c+64*(2jp+1).
        const int tr2 = tid >> 6;      // t-tile 0..7
        const int c   = tid & 63;      // column lane 0..63
        const int t0  = tr2 * 4;
        unsigned long long accp2[4][4];
        #pragma unroll
        for (int i = 0; i < 4; i++)
            #pragma unroll
            for (int jp = 0; jp < 4; jp++) accp2[i][jp] = 0ull;

        #pragma unroll 2
        for (int o = 0; o < 36; o++) {
            float4 a = *(const float4*)&att_ts[o * 36 + t0];   // warp-uniform broadcast
            unsigned long long avp[4] = {
                packf2(a.x, a.x), packf2(a.y, a.y), packf2(a.z, a.z), packf2(a.w, a.w)
            };
            unsigned long long ovp[4];
            #pragma unroll
            for (int jp = 0; jp < 4; jp++)
                ovp[jp] = packf2(o_s[o * DD + c + 128 * jp],
                                 o_s[o * DD + c + 128 * jp + 64]);   // dense scalar LDS
            #pragma unroll
            for (int i = 0; i < 4; i++)
                #pragma unroll
                for (int jp = 0; jp < 4; jp++)
                    fma2(accp2[i][jp], avp[i], ovp[jp]);
        }

        // unpack to the round-8 layout: acc2[i][j], j=2jp -> d=c+64j
        float acc2[4][8];
        #pragma unroll
        for (int i = 0; i < 4; i++)
            #pragma unroll
            for (int jp = 0; jp < 4; jp++)
                unpackf2(accp2[i][jp], acc2[i][2 * jp], acc2[i][2 * jp + 1]);

        // dense warp STG.32 stores + swizzle-aware w reads for logits
        float* avo = avo_out + ((size_t)((wb * BO + b) * TW + t0)) * DD;
        const int cb = (((c >> 2) ^ tr2) << 2) + (c & 3);   // swizzled in-row float offset
        #pragma unroll
        for (int i = 0; i < 4; i++) {
            float* row = avo + (size_t)i * DD;
            #pragma unroll
            for (int j = 0; j < 8; j++)
                row[c + 64 * j] = acc2[i][j];

            const float* wr = w_s + (t0 + i) * 512 + cb;
            float l = 0.f;
            #pragma unroll
            for (int j = 0; j < 8; j++)
                l += acc2[i][j] * wr[64 * j];
            #pragma unroll
            for (int off = 16; off; off >>= 1) l += __shfl_xor_sync(0xffffffffu, l, off);
            if (lane == 0) lp[(warp & 1) * 32 + (t0 + i)] = l;
        }
        __syncthreads();
        if (tid < 32)
            g_logits[((size_t)wb * TW + tid) * BO + b] = lp[tid] + lp[32 + tid];

        // ---- (H) prefetch w if wb changes ----
        if (it + 1 < cnt) {
            const int nwb = (tile + 1) >> 6;
            if (nwb != wb) {
                const float* wg = w_g + (size_t)nwb * TW * DD;
                for (int i = tid; i < TW * 128; i += 512) {
                    int t = i >> 7, k4 = i & 127;
                    cpa16(&w_s[SWZW(t, k4)], wg + t * DD + k4 * 4);
                }
                cp_commit();                        // group W
            }
        }
    }
    cp_wait0();
}

// ---- loss, stage 1: per-w masked mean of (diag - lse) ----
__global__ void cap_loss1(const int* __restrict__ mask)
{
    __shared__ float sacc[8], scnt[8];
    const int w = blockIdx.x;
    const int tid = threadIdx.x, warp = tid >> 5, lane = tid & 31;
    const float* lw = g_logits + (size_t)w * TW * BO;
    float acc = 0.f, cntv = 0.f;
    for (int t = warp; t < TW; t += 8) {
        float v0 = lw[t * BO + lane];
        float v1 = lw[t * BO + 32 + lane];
        float mx = fmaxf(v0, v1);
        #pragma unroll
        for (int off = 16; off; off >>= 1) mx = fmaxf(mx, __shfl_xor_sync(0xffffffffu, mx, off));
        float s = expf(v0 - mx) + expf(v1 - mx);
        #pragma unroll
        for (int off = 16; off; off >>= 1) s += __shfl_xor_sync(0xffffffffu, s, off);
        if (lane == 0 && mask[w * TW + t] == 0) {
            acc += lw[t * BO + w] - (mx + logf(s));
            cntv += 1.f;
        }
    }
    if (lane == 0) { sacc[warp] = acc; scnt[warp] = cntv; }
    __syncthreads();
    if (tid == 0) {
        float a = 0.f, c = 0.f;
        #pragma unroll
        for (int i = 0; i < 8; i++) { a += sacc[i]; c += scnt[i]; }
        g_wloss[w] = a / (c + 1e-6f);
    }
}

// ---- loss, stage 2: -mean over w ----
__global__ void cap_loss2(float* __restrict__ out)
{
    __shared__ float sh[2];
    const int tid = threadIdx.x, lane = tid & 31, warp = tid >> 5;
    float v = g_wloss[tid];
    #pragma unroll
    for (int off = 16; off; off >>= 1) v += __shfl_xor_sync(0xffffffffu, v, off);
    if (lane == 0) sh[warp] = v;
    __syncthreads();
    if (tid == 0) out[0] = -(sh[0] + sh[1]) * (1.0f / 64.0f);
}

extern "C" void kernel_launch(void* const* d_in, const int* in_sizes, int n_in,
                              void* d_out, int out_size)
{
    (void)in_sizes; (void)n_in; (void)out_size;
    const float* o_g  = (const float*)d_in[0];
    const float* u_g  = (const float*)d_in[1];
    const float* w_g  = (const float*)d_in[2];
    const int*   mask = (const int*)d_in[3];
    float* out = (float*)d_out;

    static int nsm = 0;
    if (nsm == 0) {
        int dev = 0;
        cudaGetDevice(&dev);
        cudaDeviceGetAttribute(&nsm, cudaDevAttrMultiProcessorCount, dev);
        if (nsm <= 0) nsm = 148;
        cudaFuncSetAttribute(cap_main, cudaFuncAttributeMaxDynamicSharedMemorySize, SMEM_BYTES);
    }

    // output layout: [0]=loss, att (Bw,Bo,Tw,To), att_V_o (Bw,Bo,Tw,D)
    float* att_out = out + 1;
    float* avo_out = out + 1 + (size_t)BW * BO * TW * TO;

    cap_main<<<nsm, 512, SMEM_BYTES>>>(o_g, u_g, w_g, att_out, avo_out);
    cap_loss1<<<64, 256>>>(mask);
    cap_loss2<<<1, 64>>>(out);
}